// round 1
// baseline (speedup 1.0000x reference)
#include <cuda_runtime.h>

#define NT 1024   // tokens (B*S)
#define ND 1024   // model dim
#define NH 512    // hidden dim
#define NE 8      // experts

// ---- static scratch (no allocations allowed) ----
__device__ int   g_cnt[NE];
__device__ int   g_tok[NE * NT];
__device__ float g_scl[NE * NT];
__device__ float g_h[(size_t)NE * NT * NH];   // padded per-expert hidden activations (16.8 MB)

// ---------------------------------------------------------------------------
// init: zero output (each element gets exactly 2 atomic contributions later)
// and zero the expert counters.
// ---------------------------------------------------------------------------
__global__ void init_kernel(float* __restrict__ out) {
    int tid = blockIdx.x * blockDim.x + threadIdx.x;
    if (tid < NE) g_cnt[tid] = 0;
    int stride = gridDim.x * blockDim.x;
    for (int i = tid; i < NT * ND; i += stride) out[i] = 0.f;
}

// ---------------------------------------------------------------------------
// router: one warp per token. logits = x @ gate_w, softmax over 8, top-2,
// append (token, score) to each chosen expert's list.
// ---------------------------------------------------------------------------
__global__ void router_kernel(const float* __restrict__ x,
                              const float* __restrict__ gw) {
    int gwarp = (blockIdx.x * blockDim.x + threadIdx.x) >> 5;
    int lane  = threadIdx.x & 31;
    if (gwarp >= NT) return;
    const float* xr = x + (size_t)gwarp * ND;
    float acc[NE];
#pragma unroll
    for (int e = 0; e < NE; e++) acc[e] = 0.f;
    for (int d = lane; d < ND; d += 32) {
        float xv = xr[d];
        const float* g = gw + d * NE;
#pragma unroll
        for (int e = 0; e < NE; e++) acc[e] = fmaf(xv, g[e], acc[e]);
    }
#pragma unroll
    for (int e = 0; e < NE; e++)
#pragma unroll
        for (int o = 16; o > 0; o >>= 1)
            acc[e] += __shfl_xor_sync(0xffffffffu, acc[e], o);

    if (lane == 0) {
        float m = acc[0];
#pragma unroll
        for (int e = 1; e < NE; e++) m = fmaxf(m, acc[e]);
        float Z = 0.f, p[NE];
#pragma unroll
        for (int e = 0; e < NE; e++) { p[e] = __expf(acc[e] - m); Z += p[e]; }
        int i1 = 0;
#pragma unroll
        for (int e = 1; e < NE; e++) if (p[e] > p[i1]) i1 = e;
        int i2 = (i1 == 0) ? 1 : 0;
#pragma unroll
        for (int e = 0; e < NE; e++) if (e != i1 && p[e] > p[i2]) i2 = e;
        float invZ = 1.f / Z;
        int pos = atomicAdd(&g_cnt[i1], 1);
        g_tok[i1 * NT + pos] = gwarp; g_scl[i1 * NT + pos] = p[i1] * invZ;
        pos = atomicAdd(&g_cnt[i2], 1);
        g_tok[i2 * NT + pos] = gwarp; g_scl[i2 * NT + pos] = p[i2] * invZ;
    }
}

// ---------------------------------------------------------------------------
// gemm1: per-expert grouped GEMM. A = scale * x[gathered rows]  [cnt, 1024]
// B1 = w1[e] [1024,512], B3 = w3[e] [1024,512]. Shares the A tile between the
// two products; epilogue h = silu(A@B1) * (A@B3) -> g_h.
// Tiles: 64(M) x 64(N) x 16(K), 256 threads, 4x4 micro-tile per thread.
// ---------------------------------------------------------------------------
__global__ __launch_bounds__(256) void gemm1_kernel(
    const float* __restrict__ x,
    const float* __restrict__ w1,
    const float* __restrict__ w3) {
    const int e     = blockIdx.x >> 4;
    const int mt    = blockIdx.x & 15;
    const int nt    = blockIdx.y;            // 0..7
    const int cnt   = g_cnt[e];
    const int m0blk = mt * 64;
    if (m0blk >= cnt) return;

    __shared__ float As[16][64];
    __shared__ float B1s[16][64];
    __shared__ float B3s[16][64];

    const int tid = threadIdx.x;
    // A-load mapping: thread -> (row in tile, k-quad)
    const int aml = tid >> 2;                // 0..63
    const int akk = tid & 3;                 // 0..3
    const int arow = m0blk + aml;
    const bool avalid = (arow < cnt);
    const int   atok = avalid ? g_tok[e * NT + arow] : 0;
    const float ascl = avalid ? g_scl[e * NT + arow] : 0.f;
    const float* aptr = x + (size_t)atok * ND + akk * 4;

    // B-load mapping: thread -> (k row, n-quad)
    const int bk  = tid >> 4;                // 0..15
    const int bn4 = tid & 15;                // 0..15
    const float* b1ptr = w1 + ((size_t)e * ND + bk) * NH + nt * 64 + bn4 * 4;
    const float* b3ptr = w3 + ((size_t)e * ND + bk) * NH + nt * 64 + bn4 * 4;

    const int tm = tid >> 4;                 // 0..15 -> rows tm*4..+3
    const int tn = tid & 15;                 // 0..15 -> cols tn*4..+3

    float acc1[4][4], acc3[4][4];
#pragma unroll
    for (int i = 0; i < 4; i++)
#pragma unroll
        for (int j = 0; j < 4; j++) { acc1[i][j] = 0.f; acc3[i][j] = 0.f; }

    for (int kt = 0; kt < ND / 16; kt++) {
        float4 av  = avalid ? *(const float4*)(aptr + kt * 16)
                            : make_float4(0.f, 0.f, 0.f, 0.f);
        float4 b1v = *(const float4*)(b1ptr + (size_t)kt * 16 * NH);
        float4 b3v = *(const float4*)(b3ptr + (size_t)kt * 16 * NH);
        __syncthreads();
        As[akk * 4 + 0][aml] = av.x * ascl;
        As[akk * 4 + 1][aml] = av.y * ascl;
        As[akk * 4 + 2][aml] = av.z * ascl;
        As[akk * 4 + 3][aml] = av.w * ascl;
        *(float4*)&B1s[bk][bn4 * 4] = b1v;
        *(float4*)&B3s[bk][bn4 * 4] = b3v;
        __syncthreads();
#pragma unroll
        for (int k = 0; k < 16; k++) {
            float4 a  = *(const float4*)&As[k][tm * 4];
            float4 b1 = *(const float4*)&B1s[k][tn * 4];
            float4 b3 = *(const float4*)&B3s[k][tn * 4];
            float aa[4]  = {a.x, a.y, a.z, a.w};
            float bb1[4] = {b1.x, b1.y, b1.z, b1.w};
            float bb3[4] = {b3.x, b3.y, b3.z, b3.w};
#pragma unroll
            for (int i = 0; i < 4; i++)
#pragma unroll
                for (int j = 0; j < 4; j++) {
                    acc1[i][j] = fmaf(aa[i], bb1[j], acc1[i][j]);
                    acc3[i][j] = fmaf(aa[i], bb3[j], acc3[i][j]);
                }
        }
    }

    // epilogue: h = silu(g) * u
#pragma unroll
    for (int i = 0; i < 4; i++) {
        int row = m0blk + tm * 4 + i;
        if (row < cnt) {
            float4 hv;
            float v;
            v = acc1[i][0]; hv.x = (v / (1.f + __expf(-v))) * acc3[i][0];
            v = acc1[i][1]; hv.y = (v / (1.f + __expf(-v))) * acc3[i][1];
            v = acc1[i][2]; hv.z = (v / (1.f + __expf(-v))) * acc3[i][2];
            v = acc1[i][3]; hv.w = (v / (1.f + __expf(-v))) * acc3[i][3];
            *(float4*)&g_h[((size_t)e * NT + row) * NH + nt * 64 + tn * 4] = hv;
        }
    }
}

// ---------------------------------------------------------------------------
// gemm2: y = h @ w2[e], scatter-combined into out via atomicAdd.
// Each out element receives exactly 2 contributions (top-2) -> commutative,
// bitwise-deterministic result. Tiles 64x64x16.
// ---------------------------------------------------------------------------
__global__ __launch_bounds__(256) void gemm2_kernel(
    const float* __restrict__ w2, float* __restrict__ out) {
    const int e     = blockIdx.x >> 4;
    const int mt    = blockIdx.x & 15;
    const int nt    = blockIdx.y;            // 0..15
    const int cnt   = g_cnt[e];
    const int m0blk = mt * 64;
    if (m0blk >= cnt) return;

    __shared__ float As[16][64];
    __shared__ float Bs[16][64];

    const int tid = threadIdx.x;
    const int aml = tid >> 2;
    const int akk = tid & 3;
    const int arow = m0blk + aml;
    const bool avalid = (arow < cnt);
    const float* aptr = &g_h[((size_t)e * NT + (avalid ? arow : 0)) * NH + akk * 4];

    const int bk  = tid >> 4;
    const int bn4 = tid & 15;
    const float* bptr = w2 + ((size_t)e * NH + bk) * ND + nt * 64 + bn4 * 4;

    const int tm = tid >> 4;
    const int tn = tid & 15;
    float acc[4][4];
#pragma unroll
    for (int i = 0; i < 4; i++)
#pragma unroll
        for (int j = 0; j < 4; j++) acc[i][j] = 0.f;

    for (int kt = 0; kt < NH / 16; kt++) {
        float4 av = avalid ? *(const float4*)(aptr + kt * 16)
                           : make_float4(0.f, 0.f, 0.f, 0.f);
        float4 bv = *(const float4*)(bptr + (size_t)kt * 16 * ND);
        __syncthreads();
        As[akk * 4 + 0][aml] = av.x;
        As[akk * 4 + 1][aml] = av.y;
        As[akk * 4 + 2][aml] = av.z;
        As[akk * 4 + 3][aml] = av.w;
        *(float4*)&Bs[bk][bn4 * 4] = bv;
        __syncthreads();
#pragma unroll
        for (int k = 0; k < 16; k++) {
            float4 a = *(const float4*)&As[k][tm * 4];
            float4 b = *(const float4*)&Bs[k][tn * 4];
            float aa[4] = {a.x, a.y, a.z, a.w};
            float bb[4] = {b.x, b.y, b.z, b.w};
#pragma unroll
            for (int i = 0; i < 4; i++)
#pragma unroll
                for (int j = 0; j < 4; j++)
                    acc[i][j] = fmaf(aa[i], bb[j], acc[i][j]);
        }
    }

#pragma unroll
    for (int i = 0; i < 4; i++) {
        int row = m0blk + tm * 4 + i;
        if (row < cnt) {
            int tok = g_tok[e * NT + row];
            float* op = out + (size_t)tok * ND + nt * 64 + tn * 4;
            atomicAdd(op + 0, acc[i][0]);
            atomicAdd(op + 1, acc[i][1]);
            atomicAdd(op + 2, acc[i][2]);
            atomicAdd(op + 3, acc[i][3]);
        }
    }
}

// ---------------------------------------------------------------------------
extern "C" void kernel_launch(void* const* d_in, const int* in_sizes, int n_in,
                              void* d_out, int out_size) {
    (void)in_sizes; (void)n_in; (void)out_size;
    const float* x  = (const float*)d_in[0];
    const float* gw = (const float*)d_in[1];
    const float* w1 = (const float*)d_in[2];
    const float* w2 = (const float*)d_in[3];
    const float* w3 = (const float*)d_in[4];
    float* out = (float*)d_out;

    init_kernel<<<256, 256>>>(out);
    router_kernel<<<NT / 8, 256>>>(x, gw);                 // 8 warps/block
    gemm1_kernel<<<dim3(NE * 16, NH / 64), 256>>>(x, w1, w3);
    gemm2_kernel<<<dim3(NE * 16, ND / 64), 256>>>(w2, out);
}

// round 4
// speedup vs baseline: 1.0852x; 1.0852x over previous
#include <cuda_runtime.h>
#include <cstdint>

#define NT 1024   // tokens
#define ND 1024   // model dim
#define NH 512    // hidden dim
#define NE 8      // experts

// ---- static scratch ----
__device__ int   g_cnt[NE];
__device__ int   g_tok[NE * NT];
__device__ float g_scl[NE * NT];
__device__ int   g_slot[2 * NT];
__device__ float g_h[(size_t)NE * NT * NH];   // 16.8 MB
__device__ float g_y[(size_t)NE * NT * ND];   // 33.6 MB

// ===================== helpers =====================
__device__ __forceinline__ uint32_t cvt_tf32(float f) {
    uint32_t u;
    asm("cvt.rna.tf32.f32 %0, %1;" : "=r"(u) : "f"(f));
    return u;
}
// exact split: v = hi + residual; both rounded to tf32
__device__ __forceinline__ void split_tf32(float v, uint32_t& hi, uint32_t& lo) {
    hi = cvt_tf32(v);
    lo = cvt_tf32(v - __uint_as_float(hi));
}
__device__ __forceinline__ void mma_tf32(float* c, const uint32_t* a, uint32_t b0, uint32_t b1) {
    asm volatile(
        "mma.sync.aligned.m16n8k8.row.col.f32.tf32.tf32.f32 "
        "{%0,%1,%2,%3}, {%4,%5,%6,%7}, {%8,%9}, {%0,%1,%2,%3};"
        : "+f"(c[0]), "+f"(c[1]), "+f"(c[2]), "+f"(c[3])
        : "r"(a[0]), "r"(a[1]), "r"(a[2]), "r"(a[3]), "r"(b0), "r"(b1));
}
__device__ __forceinline__ void cp16(uint32_t s, const void* g) {
    asm volatile("cp.async.cg.shared.global [%0], [%1], 16;" :: "r"(s), "l"(g));
}
#define CP_COMMIT() asm volatile("cp.async.commit_group;")
#define CP_WAIT(n)  asm volatile("cp.async.wait_group %0;" :: "n"(n))

// ===================== init + router =====================
__global__ void init_kernel() {
    if (threadIdx.x < NE) g_cnt[threadIdx.x] = 0;
}

__global__ void router_kernel(const float* __restrict__ x,
                              const float* __restrict__ gw) {
    int t    = (blockIdx.x * blockDim.x + threadIdx.x) >> 5;
    int lane = threadIdx.x & 31;
    if (t >= NT) return;
    const float* xr = x + (size_t)t * ND;
    float acc[NE];
#pragma unroll
    for (int e = 0; e < NE; e++) acc[e] = 0.f;
    for (int d = lane; d < ND; d += 32) {
        float xv = xr[d];
        const float* g = gw + d * NE;
#pragma unroll
        for (int e = 0; e < NE; e++) acc[e] = fmaf(xv, g[e], acc[e]);
    }
#pragma unroll
    for (int e = 0; e < NE; e++)
#pragma unroll
        for (int o = 16; o > 0; o >>= 1)
            acc[e] += __shfl_xor_sync(0xffffffffu, acc[e], o);
    if (lane == 0) {
        float m = acc[0];
#pragma unroll
        for (int e = 1; e < NE; e++) m = fmaxf(m, acc[e]);
        float Z = 0.f, p[NE];
#pragma unroll
        for (int e = 0; e < NE; e++) { p[e] = __expf(acc[e] - m); Z += p[e]; }
        int i1 = 0;
#pragma unroll
        for (int e = 1; e < NE; e++) if (p[e] > p[i1]) i1 = e;
        int i2 = (i1 == 0) ? 1 : 0;
#pragma unroll
        for (int e = 0; e < NE; e++) if (e != i1 && p[e] > p[i2]) i2 = e;
        float invZ = 1.f / Z;
        int pos = atomicAdd(&g_cnt[i1], 1);
        g_tok[i1 * NT + pos] = t; g_scl[i1 * NT + pos] = p[i1] * invZ;
        g_slot[2 * t] = i1 * NT + pos;
        pos = atomicAdd(&g_cnt[i2], 1);
        g_tok[i2 * NT + pos] = t; g_scl[i2 * NT + pos] = p[i2] * invZ;
        g_slot[2 * t + 1] = i2 * NT + pos;
    }
}

// ===================== gemm1: 3xTF32 mma.sync, fused SwiGLU =====================
// CTA: M=64 tokens x 128 hidden; 8 warps 2(M)x4(N); warp tile 32x32 dual acc.
// All smem offsets in FLOATS. A stride 36, B stride 136, double buffered.
#define A_STR   36
#define B_STR   136
#define G1_B1F  2304                 // 64*36
#define G1_B3F  (G1_B1F + 32*B_STR)  // 2304+4352 = 6656
#define G1_BUFF (G1_B3F + 32*B_STR)  // 11008 floats = 44032 B

__global__ __launch_bounds__(256) void gemm1_tc(
    const float* __restrict__ x,
    const float* __restrict__ w1,
    const float* __restrict__ w3) {
    const int e   = blockIdx.x >> 4;
    const int mt  = blockIdx.x & 15;
    const int cnt = g_cnt[e];
    const int m0  = mt * 64;
    if (m0 >= cnt) return;
    const int hb = blockIdx.y * 128;

    extern __shared__ float sm[];
    const uint32_t sbase = (uint32_t)__cvta_generic_to_shared(sm);
    const int tid = threadIdx.x, wid = tid >> 5, lane = tid & 31;
    const int ty = lane >> 2, tx = lane & 3;
    const int warpM = (wid & 1) * 32, warpN = (wid >> 1) * 32;

    const int arow = tid >> 2;
    const int aq   = (tid & 3) * 8;
    const int gr   = m0 + arow;
    const bool av  = gr < cnt;
    const float scl = av ? g_scl[e * NT + gr] : 0.f;
    const float* ag = x + (size_t)(av ? g_tok[e * NT + gr] : 0) * ND + aq;
    float* asm0 = sm + arow * A_STR + aq;

    const int brow = tid >> 3;
    const int bcs  = (tid & 7) * 16;
    const float* b1g = w1 + ((size_t)e * ND + brow) * NH + hb + bcs;
    const float* b3g = w3 + ((size_t)e * ND + brow) * NH + hb + bcs;
    const uint32_t b1s = sbase + (G1_B1F + brow * B_STR + bcs) * 4;
    const uint32_t b3s = sbase + (G1_B3F + brow * B_STR + bcs) * 4;

    float a1[2][4][4], a3[2][4][4];
#pragma unroll
    for (int m = 0; m < 2; m++)
#pragma unroll
        for (int n = 0; n < 4; n++)
#pragma unroll
            for (int r = 0; r < 4; r++) { a1[m][n][r] = 0.f; a3[m][n][r] = 0.f; }

    float areg[8];

#pragma unroll
    for (int j = 0; j < 4; j++) {
        cp16(b1s + j * 16, b1g + j * 4);
        cp16(b3s + j * 16, b3g + j * 4);
    }
    CP_COMMIT();
    {
        float4 v0 = *(const float4*)(ag);
        float4 v1 = *(const float4*)(ag + 4);
        *(float4*)(asm0)     = make_float4(v0.x*scl, v0.y*scl, v0.z*scl, v0.w*scl);
        *(float4*)(asm0 + 4) = make_float4(v1.x*scl, v1.y*scl, v1.z*scl, v1.w*scl);
    }

    const int NC = ND / 32;
    for (int kt = 0; kt < NC; kt++) {
        const int b = kt & 1;
        const bool nxt = (kt + 1) < NC;
        if (nxt) {
            const uint32_t bo = (b ^ 1) * G1_BUFF * 4;
            const float* s1 = b1g + (size_t)(kt + 1) * 32 * NH;
            const float* s3 = b3g + (size_t)(kt + 1) * 32 * NH;
#pragma unroll
            for (int j = 0; j < 4; j++) {
                cp16(b1s + bo + j * 16, s1 + j * 4);
                cp16(b3s + bo + j * 16, s3 + j * 4);
            }
            CP_COMMIT();
            float4 v0 = *(const float4*)(ag + (kt + 1) * 32);
            float4 v1 = *(const float4*)(ag + (kt + 1) * 32 + 4);
            areg[0]=v0.x*scl; areg[1]=v0.y*scl; areg[2]=v0.z*scl; areg[3]=v0.w*scl;
            areg[4]=v1.x*scl; areg[5]=v1.y*scl; areg[6]=v1.z*scl; areg[7]=v1.w*scl;
            CP_WAIT(1);
        } else {
            CP_WAIT(0);
        }
        __syncthreads();

        const float* Af  = sm + b * G1_BUFF;
        const float* B1f = Af + G1_B1F;
        const float* B3f = Af + G1_B3F;
#pragma unroll
        for (int k8 = 0; k8 < 4; k8++) {
            uint32_t ah[2][4], al[2][4];
#pragma unroll
            for (int m = 0; m < 2; m++) {
                const float* p = Af + (warpM + m * 16 + ty) * A_STR + k8 * 8 + tx;
                split_tf32(p[0],             ah[m][0], al[m][0]);
                split_tf32(p[8 * A_STR],     ah[m][1], al[m][1]);
                split_tf32(p[4],             ah[m][2], al[m][2]);
                split_tf32(p[8 * A_STR + 4], ah[m][3], al[m][3]);
            }
#pragma unroll
            for (int n = 0; n < 4; n++) {
                const float* q1 = B1f + (k8 * 8 + tx) * B_STR + warpN + n * 8 + ty;
                uint32_t bh0, bl0, bh1, bl1;
                split_tf32(q1[0],         bh0, bl0);
                split_tf32(q1[4 * B_STR], bh1, bl1);
#pragma unroll
                for (int m = 0; m < 2; m++) {
                    mma_tf32(a1[m][n], ah[m], bh0, bh1);
                    mma_tf32(a1[m][n], al[m], bh0, bh1);
                    mma_tf32(a1[m][n], ah[m], bl0, bl1);
                }
                const float* q3 = B3f + (k8 * 8 + tx) * B_STR + warpN + n * 8 + ty;
                split_tf32(q3[0],         bh0, bl0);
                split_tf32(q3[4 * B_STR], bh1, bl1);
#pragma unroll
                for (int m = 0; m < 2; m++) {
                    mma_tf32(a3[m][n], ah[m], bh0, bh1);
                    mma_tf32(a3[m][n], al[m], bh0, bh1);
                    mma_tf32(a3[m][n], ah[m], bl0, bl1);
                }
            }
        }
        __syncthreads();
        if (nxt) {
            float* dst = sm + (b ^ 1) * G1_BUFF + arow * A_STR + aq;
            *(float4*)(dst)     = make_float4(areg[0], areg[1], areg[2], areg[3]);
            *(float4*)(dst + 4) = make_float4(areg[4], areg[5], areg[6], areg[7]);
        }
    }

#pragma unroll
    for (int m = 0; m < 2; m++) {
        const int r = m0 + warpM + m * 16 + ty;
#pragma unroll
        for (int n = 0; n < 4; n++) {
            const int col = hb + warpN + n * 8 + tx * 2;
            if (r < cnt) {
                float g0 = a1[m][n][0], u0 = a3[m][n][0];
                float g1 = a1[m][n][1], u1 = a3[m][n][1];
                *(float2*)&g_h[((size_t)e * NT + r) * NH + col] =
                    make_float2((g0 / (1.f + __expf(-g0))) * u0,
                                (g1 / (1.f + __expf(-g1))) * u1);
            }
            if (r + 8 < cnt) {
                float g0 = a1[m][n][2], u0 = a3[m][n][2];
                float g1 = a1[m][n][3], u1 = a3[m][n][3];
                *(float2*)&g_h[((size_t)e * NT + r + 8) * NH + col] =
                    make_float2((g0 / (1.f + __expf(-g0))) * u0,
                                (g1 / (1.f + __expf(-g1))) * u1);
            }
        }
    }
}

// ===================== gemm2: y = h @ w2 (3xTF32) =====================
// CTA: M=64 x N=256; 8 warps 2x4; warp tile 32x64. Offsets in FLOATS.
#define B2_STR  264
#define G2_BF   2304                  // 64*36
#define G2_BUFF (G2_BF + 32*B2_STR)   // 2304+8448 = 10752 floats

__global__ __launch_bounds__(256) void gemm2_tc(const float* __restrict__ w2) {
    const int e   = blockIdx.x >> 4;
    const int mt  = blockIdx.x & 15;
    const int cnt = g_cnt[e];
    const int m0  = mt * 64;
    if (m0 >= cnt) return;
    const int dbase = blockIdx.y * 256;

    extern __shared__ float sm[];
    const uint32_t sbase = (uint32_t)__cvta_generic_to_shared(sm);
    const int tid = threadIdx.x, wid = tid >> 5, lane = tid & 31;
    const int ty = lane >> 2, tx = lane & 3;
    const int warpM = (wid & 1) * 32, warpN = (wid >> 1) * 64;

    const int arow = tid >> 2;
    const int aq   = (tid & 3) * 8;
    const float* agl = &g_h[((size_t)e * NT + m0 + arow) * NH + aq];
    const uint32_t as = sbase + (arow * A_STR + aq) * 4;

    const int brow = tid >> 3;
    const int bcs  = (tid & 7) * 32;
    const float* bgl = w2 + ((size_t)e * NH + brow) * ND + dbase + bcs;
    const uint32_t bs = sbase + (G2_BF + brow * B2_STR + bcs) * 4;

    float acc[2][8][4];
#pragma unroll
    for (int m = 0; m < 2; m++)
#pragma unroll
        for (int n = 0; n < 8; n++)
#pragma unroll
            for (int r = 0; r < 4; r++) acc[m][n][r] = 0.f;

#pragma unroll
    for (int j = 0; j < 2; j++) cp16(as + j * 16, agl + j * 4);
#pragma unroll
    for (int j = 0; j < 8; j++) cp16(bs + j * 16, bgl + j * 4);
    CP_COMMIT();

    const int NC = NH / 32;
    for (int kt = 0; kt < NC; kt++) {
        const int b = kt & 1;
        const bool nxt = (kt + 1) < NC;
        if (nxt) {
            const uint32_t bo = (b ^ 1) * G2_BUFF * 4;
            const float* an = agl + (kt + 1) * 32;
            const float* bn = bgl + (size_t)(kt + 1) * 32 * ND;
#pragma unroll
            for (int j = 0; j < 2; j++) cp16(as + bo + j * 16, an + j * 4);
#pragma unroll
            for (int j = 0; j < 8; j++) cp16(bs + bo + j * 16, bn + j * 4);
            CP_COMMIT();
            CP_WAIT(1);
        } else {
            CP_WAIT(0);
        }
        __syncthreads();

        const float* Af = sm + b * G2_BUFF;
        const float* Bf = Af + G2_BF;
#pragma unroll
        for (int k8 = 0; k8 < 4; k8++) {
            uint32_t ah[2][4], al[2][4];
#pragma unroll
            for (int m = 0; m < 2; m++) {
                const float* p = Af + (warpM + m * 16 + ty) * A_STR + k8 * 8 + tx;
                split_tf32(p[0],             ah[m][0], al[m][0]);
                split_tf32(p[8 * A_STR],     ah[m][1], al[m][1]);
                split_tf32(p[4],             ah[m][2], al[m][2]);
                split_tf32(p[8 * A_STR + 4], ah[m][3], al[m][3]);
            }
#pragma unroll
            for (int n = 0; n < 8; n++) {
                const float* q = Bf + (k8 * 8 + tx) * B2_STR + warpN + n * 8 + ty;
                uint32_t bh0, bl0, bh1, bl1;
                split_tf32(q[0],          bh0, bl0);
                split_tf32(q[4 * B2_STR], bh1, bl1);
#pragma unroll
                for (int m = 0; m < 2; m++) {
                    mma_tf32(acc[m][n], ah[m], bh0, bh1);
                    mma_tf32(acc[m][n], al[m], bh0, bh1);
                    mma_tf32(acc[m][n], ah[m], bl0, bl1);
                }
            }
        }
        __syncthreads();
    }

#pragma unroll
    for (int m = 0; m < 2; m++) {
        const int r = m0 + warpM + m * 16 + ty;
#pragma unroll
        for (int n = 0; n < 8; n++) {
            const int col = dbase + warpN + n * 8 + tx * 2;
            if (r < cnt)
                *(float2*)&g_y[((size_t)e * NT + r) * ND + col] =
                    make_float2(acc[m][n][0], acc[m][n][1]);
            if (r + 8 < cnt)
                *(float2*)&g_y[((size_t)e * NT + r + 8) * ND + col] =
                    make_float2(acc[m][n][2], acc[m][n][3]);
        }
    }
}

// ===================== combine =====================
__global__ void combine_kernel(float* __restrict__ out) {
    int i = blockIdx.x * blockDim.x + threadIdx.x;
    int t = i >> 8;
    int d = (i & 255) * 4;
    int s1 = g_slot[2 * t], s2 = g_slot[2 * t + 1];
    float4 a = *(const float4*)&g_y[(size_t)s1 * ND + d];
    float4 b = *(const float4*)&g_y[(size_t)s2 * ND + d];
    *(float4*)&out[(size_t)t * ND + d] =
        make_float4(a.x + b.x, a.y + b.y, a.z + b.z, a.w + b.w);
}

// ===================== launch =====================
extern "C" void kernel_launch(void* const* d_in, const int* in_sizes, int n_in,
                              void* d_out, int out_size) {
    (void)in_sizes; (void)n_in; (void)out_size;
    const float* x  = (const float*)d_in[0];
    const float* gw = (const float*)d_in[1];
    const float* w1 = (const float*)d_in[2];
    const float* w2 = (const float*)d_in[3];
    const float* w3 = (const float*)d_in[4];
    float* out = (float*)d_out;

    const int SMEM1 = 2 * G1_BUFF * (int)sizeof(float);   // 88064 B
    const int SMEM2 = 2 * G2_BUFF * (int)sizeof(float);   // 86016 B
    cudaFuncSetAttribute(gemm1_tc, cudaFuncAttributeMaxDynamicSharedMemorySize, SMEM1);
    cudaFuncSetAttribute(gemm2_tc, cudaFuncAttributeMaxDynamicSharedMemorySize, SMEM2);

    init_kernel<<<1, 32>>>();
    router_kernel<<<NT / 8, 256>>>(x, gw);
    gemm1_tc<<<dim3(NE * 16, NH / 128), 256, SMEM1>>>(x, w1, w3);
    gemm2_tc<<<dim3(NE * 16, ND / 256), 256, SMEM2>>>(w2);
    combine_kernel<<<NT * ND / 4 / 256, 256>>>(out);
}

// round 5
// speedup vs baseline: 1.6502x; 1.5207x over previous
#include <cuda_runtime.h>
#include <cstdint>

#define NT 1024   // tokens
#define ND 1024   // model dim
#define NH 512    // hidden dim
#define NE 8     // experts

// ---- static scratch ----
__device__ int   g_cnt[NE];
__device__ int   g_tok[NE * NT];
__device__ float g_scl[NE * NT];
__device__ int   g_slot[2 * NT];
__device__ float g_h[(size_t)NE * NT * NH];   // 16.8 MB
__device__ float g_y[(size_t)NE * NT * ND];   // 33.6 MB

// ===================== helpers =====================
__device__ __forceinline__ uint32_t cvt_tf32(float f) {
    uint32_t u;
    asm("cvt.rna.tf32.f32 %0, %1;" : "=r"(u) : "f"(f));
    return u;
}
__device__ __forceinline__ void split_tf32(float v, uint32_t& hi, uint32_t& lo) {
    hi = cvt_tf32(v);
    lo = cvt_tf32(v - __uint_as_float(hi));
}
__device__ __forceinline__ void mma_tf32(float* c, const uint32_t* a, uint32_t b0, uint32_t b1) {
    asm volatile(
        "mma.sync.aligned.m16n8k8.row.col.f32.tf32.tf32.f32 "
        "{%0,%1,%2,%3}, {%4,%5,%6,%7}, {%8,%9}, {%0,%1,%2,%3};"
        : "+f"(c[0]), "+f"(c[1]), "+f"(c[2]), "+f"(c[3])
        : "r"(a[0]), "r"(a[1]), "r"(a[2]), "r"(a[3]), "r"(b0), "r"(b1));
}
__device__ __forceinline__ void cp16(uint32_t s, const void* g) {
    asm volatile("cp.async.cg.shared.global [%0], [%1], 16;" :: "r"(s), "l"(g));
}
#define CP_COMMIT() asm volatile("cp.async.commit_group;")
#define CP_WAIT(n)  asm volatile("cp.async.wait_group %0;" :: "n"(n))

// ===================== init + router =====================
__global__ void init_kernel() {
    if (threadIdx.x < NE) g_cnt[threadIdx.x] = 0;
}

__global__ void router_kernel(const float* __restrict__ x,
                              const float* __restrict__ gw) {
    int t    = (blockIdx.x * blockDim.x + threadIdx.x) >> 5;
    int lane = threadIdx.x & 31;
    if (t >= NT) return;
    const float* xr = x + (size_t)t * ND;
    float acc[NE];
#pragma unroll
    for (int e = 0; e < NE; e++) acc[e] = 0.f;
    for (int d = lane; d < ND; d += 32) {
        float xv = xr[d];
        const float* g = gw + d * NE;
#pragma unroll
        for (int e = 0; e < NE; e++) acc[e] = fmaf(xv, g[e], acc[e]);
    }
#pragma unroll
    for (int e = 0; e < NE; e++)
#pragma unroll
        for (int o = 16; o > 0; o >>= 1)
            acc[e] += __shfl_xor_sync(0xffffffffu, acc[e], o);
    if (lane == 0) {
        float m = acc[0];
#pragma unroll
        for (int e = 1; e < NE; e++) m = fmaxf(m, acc[e]);
        float Z = 0.f, p[NE];
#pragma unroll
        for (int e = 0; e < NE; e++) { p[e] = __expf(acc[e] - m); Z += p[e]; }
        int i1 = 0;
#pragma unroll
        for (int e = 1; e < NE; e++) if (p[e] > p[i1]) i1 = e;
        int i2 = (i1 == 0) ? 1 : 0;
#pragma unroll
        for (int e = 0; e < NE; e++) if (e != i1 && p[e] > p[i2]) i2 = e;
        float invZ = 1.f / Z;
        int pos = atomicAdd(&g_cnt[i1], 1);
        g_tok[i1 * NT + pos] = t; g_scl[i1 * NT + pos] = p[i1] * invZ;
        g_slot[2 * t] = i1 * NT + pos;
        pos = atomicAdd(&g_cnt[i2], 1);
        g_tok[i2 * NT + pos] = t; g_scl[i2 * NT + pos] = p[i2] * invZ;
        g_slot[2 * t + 1] = i2 * NT + pos;
    }
}

// ===================== gemm1: 3xTF32, pre-split A, fused SwiGLU =====================
// CTA: M=64 x H=64 (both w1 and w3). 8 warps 2(M)x4(N); warp 32x16 per matrix.
// smem floats/buffer: AH 2304 | AL 2304 | B1 2304 | B3 2304 = 9216 (36,864 B), x2 buffers.
#define A_STR   36
#define B1_STR  72
#define G1_ALF  2304
#define G1_B1F  4608
#define G1_B3F  6912
#define G1_BUFF 9216

__global__ __launch_bounds__(256) void gemm1_tc(
    const float* __restrict__ x,
    const float* __restrict__ w1,
    const float* __restrict__ w3) {
    const int e   = blockIdx.x >> 4;
    const int mt  = blockIdx.x & 15;
    const int cnt = g_cnt[e];
    const int m0  = mt * 64;
    if (m0 >= cnt) return;
    const int hb = blockIdx.y * 64;

    extern __shared__ float sm[];
    const uint32_t sbase = (uint32_t)__cvta_generic_to_shared(sm);
    const int tid = threadIdx.x, wid = tid >> 5, lane = tid & 31;
    const int ty = lane >> 2, tx = lane & 3;
    const int warpM = (wid & 1) * 32, warpN = (wid >> 1) * 16;

    // A gather: thread -> (row 0..63, 8-float segment)
    const int arow = tid >> 2;
    const int aq   = (tid & 3) * 8;
    const int gr   = m0 + arow;
    const bool av  = gr < cnt;
    const float scl = av ? g_scl[e * NT + gr] : 0.f;
    const float* ag = x + (size_t)(av ? g_tok[e * NT + gr] : 0) * ND + aq;

    // B: thread -> (k row 0..31, 8-float segment of 64 cols)
    const int brow = tid >> 3;
    const int bcs  = (tid & 7) * 8;
    const float* b1g = w1 + ((size_t)e * ND + brow) * NH + hb + bcs;
    const float* b3g = w3 + ((size_t)e * ND + brow) * NH + hb + bcs;
    const uint32_t b1s = sbase + (G1_B1F + brow * B1_STR + bcs) * 4;
    const uint32_t b3s = sbase + (G1_B3F + brow * B1_STR + bcs) * 4;

    float a1[2][2][4], a3[2][2][4];
#pragma unroll
    for (int m = 0; m < 2; m++)
#pragma unroll
        for (int n = 0; n < 2; n++)
#pragma unroll
            for (int r = 0; r < 4; r++) { a1[m][n][r] = 0.f; a3[m][n][r] = 0.f; }

    uint32_t hreg[8], lreg[8];

    // prologue: chunk 0
#pragma unroll
    for (int j = 0; j < 2; j++) {
        cp16(b1s + j * 16, b1g + j * 4);
        cp16(b3s + j * 16, b3g + j * 4);
    }
    CP_COMMIT();
    {
        uint32_t* ah = (uint32_t*)sm + arow * A_STR + aq;
        uint32_t* al = ah + G1_ALF;
        float4 v0 = *(const float4*)(ag);
        float4 v1 = *(const float4*)(ag + 4);
        uint32_t h[8], l[8];
        split_tf32(v0.x * scl, h[0], l[0]); split_tf32(v0.y * scl, h[1], l[1]);
        split_tf32(v0.z * scl, h[2], l[2]); split_tf32(v0.w * scl, h[3], l[3]);
        split_tf32(v1.x * scl, h[4], l[4]); split_tf32(v1.y * scl, h[5], l[5]);
        split_tf32(v1.z * scl, h[6], l[6]); split_tf32(v1.w * scl, h[7], l[7]);
        *(uint4*)(ah)     = make_uint4(h[0], h[1], h[2], h[3]);
        *(uint4*)(ah + 4) = make_uint4(h[4], h[5], h[6], h[7]);
        *(uint4*)(al)     = make_uint4(l[0], l[1], l[2], l[3]);
        *(uint4*)(al + 4) = make_uint4(l[4], l[5], l[6], l[7]);
    }

    const int NC = ND / 32;
    for (int kt = 0; kt < NC; kt++) {
        const int b = kt & 1;
        const bool nxt = (kt + 1) < NC;
        if (nxt) {
            const uint32_t bo = (b ^ 1) * G1_BUFF * 4;
            const float* s1 = b1g + (size_t)(kt + 1) * 32 * NH;
            const float* s3 = b3g + (size_t)(kt + 1) * 32 * NH;
#pragma unroll
            for (int j = 0; j < 2; j++) {
                cp16(b1s + bo + j * 16, s1 + j * 4);
                cp16(b3s + bo + j * 16, s3 + j * 4);
            }
            CP_COMMIT();
            float4 v0 = *(const float4*)(ag + (kt + 1) * 32);
            float4 v1 = *(const float4*)(ag + (kt + 1) * 32 + 4);
            split_tf32(v0.x * scl, hreg[0], lreg[0]); split_tf32(v0.y * scl, hreg[1], lreg[1]);
            split_tf32(v0.z * scl, hreg[2], lreg[2]); split_tf32(v0.w * scl, hreg[3], lreg[3]);
            split_tf32(v1.x * scl, hreg[4], lreg[4]); split_tf32(v1.y * scl, hreg[5], lreg[5]);
            split_tf32(v1.z * scl, hreg[6], lreg[6]); split_tf32(v1.w * scl, hreg[7], lreg[7]);
            CP_WAIT(1);
        } else {
            CP_WAIT(0);
        }
        __syncthreads();

        const uint32_t* AH  = (const uint32_t*)sm + b * G1_BUFF;
        const uint32_t* AL  = AH + G1_ALF;
        const uint32_t* B1f = AH + G1_B1F;
        const uint32_t* B3f = AH + G1_B3F;
#pragma unroll
        for (int k8 = 0; k8 < 4; k8++) {
            uint32_t ah[2][4], al[2][4];
#pragma unroll
            for (int m = 0; m < 2; m++) {
                const int off = (warpM + m * 16 + ty) * A_STR + k8 * 8 + tx;
                ah[m][0] = AH[off];
                ah[m][1] = AH[off + 8 * A_STR];
                ah[m][2] = AH[off + 4];
                ah[m][3] = AH[off + 8 * A_STR + 4];
                al[m][0] = AL[off];
                al[m][1] = AL[off + 8 * A_STR];
                al[m][2] = AL[off + 4];
                al[m][3] = AL[off + 8 * A_STR + 4];
            }
#pragma unroll
            for (int n = 0; n < 2; n++) {
                const int boff = (k8 * 8 + tx) * B1_STR + warpN + n * 8 + ty;
                uint32_t bh0, bl0, bh1, bl1;
                split_tf32(__uint_as_float(B1f[boff]),               bh0, bl0);
                split_tf32(__uint_as_float(B1f[boff + 4 * B1_STR]),  bh1, bl1);
#pragma unroll
                for (int m = 0; m < 2; m++) {
                    mma_tf32(a1[m][n], ah[m], bh0, bh1);
                    mma_tf32(a1[m][n], al[m], bh0, bh1);
                    mma_tf32(a1[m][n], ah[m], bl0, bl1);
                }
                split_tf32(__uint_as_float(B3f[boff]),               bh0, bl0);
                split_tf32(__uint_as_float(B3f[boff + 4 * B1_STR]),  bh1, bl1);
#pragma unroll
                for (int m = 0; m < 2; m++) {
                    mma_tf32(a3[m][n], ah[m], bh0, bh1);
                    mma_tf32(a3[m][n], al[m], bh0, bh1);
                    mma_tf32(a3[m][n], ah[m], bl0, bl1);
                }
            }
        }
        __syncthreads();
        if (nxt) {
            uint32_t* ah = (uint32_t*)sm + (b ^ 1) * G1_BUFF + arow * A_STR + aq;
            uint32_t* al = ah + G1_ALF;
            *(uint4*)(ah)     = make_uint4(hreg[0], hreg[1], hreg[2], hreg[3]);
            *(uint4*)(ah + 4) = make_uint4(hreg[4], hreg[5], hreg[6], hreg[7]);
            *(uint4*)(al)     = make_uint4(lreg[0], lreg[1], lreg[2], lreg[3]);
            *(uint4*)(al + 4) = make_uint4(lreg[4], lreg[5], lreg[6], lreg[7]);
        }
    }

    // epilogue: h = silu(a1) * a3 -> g_h
#pragma unroll
    for (int m = 0; m < 2; m++) {
        const int r = m0 + warpM + m * 16 + ty;
#pragma unroll
        for (int n = 0; n < 2; n++) {
            const int col = hb + warpN + n * 8 + tx * 2;
            if (r < cnt) {
                float g0 = a1[m][n][0], u0 = a3[m][n][0];
                float g1 = a1[m][n][1], u1 = a3[m][n][1];
                *(float2*)&g_h[((size_t)e * NT + r) * NH + col] =
                    make_float2((g0 / (1.f + __expf(-g0))) * u0,
                                (g1 / (1.f + __expf(-g1))) * u1);
            }
            if (r + 8 < cnt) {
                float g0 = a1[m][n][2], u0 = a3[m][n][2];
                float g1 = a1[m][n][3], u1 = a3[m][n][3];
                *(float2*)&g_h[((size_t)e * NT + r + 8) * NH + col] =
                    make_float2((g0 / (1.f + __expf(-g0))) * u0,
                                (g1 / (1.f + __expf(-g1))) * u1);
            }
        }
    }
}

// ===================== gemm2: y = h @ w2 (3xTF32, pre-split A) =====================
// CTA: M=64 x N=128. 8 warps 2x4; warp 32x32.
// smem floats/buffer: AH 2304 | AL 2304 | B 4352 = 8960 (35,840 B), x2.
#define B2_STR  136
#define G2_ALF  2304
#define G2_BF   4608
#define G2_BUFF 8960

__global__ __launch_bounds__(256) void gemm2_tc(const float* __restrict__ w2) {
    const int e   = blockIdx.x >> 4;
    const int mt  = blockIdx.x & 15;
    const int cnt = g_cnt[e];
    const int m0  = mt * 64;
    if (m0 >= cnt) return;
    const int dbase = blockIdx.y * 128;

    extern __shared__ float sm[];
    const uint32_t sbase = (uint32_t)__cvta_generic_to_shared(sm);
    const int tid = threadIdx.x, wid = tid >> 5, lane = tid & 31;
    const int ty = lane >> 2, tx = lane & 3;
    const int warpM = (wid & 1) * 32, warpN = (wid >> 1) * 32;

    const int arow = tid >> 2;
    const int aq   = (tid & 3) * 8;
    const float* agl = &g_h[((size_t)e * NT + m0 + arow) * NH + aq];

    const int brow = tid >> 3;
    const int bcs  = (tid & 7) * 16;
    const float* bgl = w2 + ((size_t)e * NH + brow) * ND + dbase + bcs;
    const uint32_t bs = sbase + (G2_BF + brow * B2_STR + bcs) * 4;

    float acc[2][4][4];
#pragma unroll
    for (int m = 0; m < 2; m++)
#pragma unroll
        for (int n = 0; n < 4; n++)
#pragma unroll
            for (int r = 0; r < 4; r++) acc[m][n][r] = 0.f;

    uint32_t hreg[8], lreg[8];

#pragma unroll
    for (int j = 0; j < 4; j++) cp16(bs + j * 16, bgl + j * 4);
    CP_COMMIT();
    {
        uint32_t* ah = (uint32_t*)sm + arow * A_STR + aq;
        uint32_t* al = ah + G2_ALF;
        float4 v0 = *(const float4*)(agl);
        float4 v1 = *(const float4*)(agl + 4);
        uint32_t h[8], l[8];
        split_tf32(v0.x, h[0], l[0]); split_tf32(v0.y, h[1], l[1]);
        split_tf32(v0.z, h[2], l[2]); split_tf32(v0.w, h[3], l[3]);
        split_tf32(v1.x, h[4], l[4]); split_tf32(v1.y, h[5], l[5]);
        split_tf32(v1.z, h[6], l[6]); split_tf32(v1.w, h[7], l[7]);
        *(uint4*)(ah)     = make_uint4(h[0], h[1], h[2], h[3]);
        *(uint4*)(ah + 4) = make_uint4(h[4], h[5], h[6], h[7]);
        *(uint4*)(al)     = make_uint4(l[0], l[1], l[2], l[3]);
        *(uint4*)(al + 4) = make_uint4(l[4], l[5], l[6], l[7]);
    }

    const int NC = NH / 32;
    for (int kt = 0; kt < NC; kt++) {
        const int b = kt & 1;
        const bool nxt = (kt + 1) < NC;
        if (nxt) {
            const uint32_t bo = (b ^ 1) * G2_BUFF * 4;
            const float* bn = bgl + (size_t)(kt + 1) * 32 * ND;
#pragma unroll
            for (int j = 0; j < 4; j++) cp16(bs + bo + j * 16, bn + j * 4);
            CP_COMMIT();
            float4 v0 = *(const float4*)(agl + (kt + 1) * 32);
            float4 v1 = *(const float4*)(agl + (kt + 1) * 32 + 4);
            split_tf32(v0.x, hreg[0], lreg[0]); split_tf32(v0.y, hreg[1], lreg[1]);
            split_tf32(v0.z, hreg[2], lreg[2]); split_tf32(v0.w, hreg[3], lreg[3]);
            split_tf32(v1.x, hreg[4], lreg[4]); split_tf32(v1.y, hreg[5], lreg[5]);
            split_tf32(v1.z, hreg[6], lreg[6]); split_tf32(v1.w, hreg[7], lreg[7]);
            CP_WAIT(1);
        } else {
            CP_WAIT(0);
        }
        __syncthreads();

        const uint32_t* AH = (const uint32_t*)sm + b * G2_BUFF;
        const uint32_t* AL = AH + G2_ALF;
        const uint32_t* Bf = AH + G2_BF;
#pragma unroll
        for (int k8 = 0; k8 < 4; k8++) {
            uint32_t ah[2][4], al[2][4];
#pragma unroll
            for (int m = 0; m < 2; m++) {
                const int off = (warpM + m * 16 + ty) * A_STR + k8 * 8 + tx;
                ah[m][0] = AH[off];
                ah[m][1] = AH[off + 8 * A_STR];
                ah[m][2] = AH[off + 4];
                ah[m][3] = AH[off + 8 * A_STR + 4];
                al[m][0] = AL[off];
                al[m][1] = AL[off + 8 * A_STR];
                al[m][2] = AL[off + 4];
                al[m][3] = AL[off + 8 * A_STR + 4];
            }
#pragma unroll
            for (int n = 0; n < 4; n++) {
                const int boff = (k8 * 8 + tx) * B2_STR + warpN + n * 8 + ty;
                uint32_t bh0, bl0, bh1, bl1;
                split_tf32(__uint_as_float(Bf[boff]),              bh0, bl0);
                split_tf32(__uint_as_float(Bf[boff + 4 * B2_STR]), bh1, bl1);
#pragma unroll
                for (int m = 0; m < 2; m++) {
                    mma_tf32(acc[m][n], ah[m], bh0, bh1);
                    mma_tf32(acc[m][n], al[m], bh0, bh1);
                    mma_tf32(acc[m][n], ah[m], bl0, bl1);
                }
            }
        }
        __syncthreads();
        if (nxt) {
            uint32_t* ah = (uint32_t*)sm + (b ^ 1) * G2_BUFF + arow * A_STR + aq;
            uint32_t* al = ah + G2_ALF;
            *(uint4*)(ah)     = make_uint4(hreg[0], hreg[1], hreg[2], hreg[3]);
            *(uint4*)(ah + 4) = make_uint4(hreg[4], hreg[5], hreg[6], hreg[7]);
            *(uint4*)(al)     = make_uint4(lreg[0], lreg[1], lreg[2], lreg[3]);
            *(uint4*)(al + 4) = make_uint4(lreg[4], lreg[5], lreg[6], lreg[7]);
        }
    }

#pragma unroll
    for (int m = 0; m < 2; m++) {
        const int r = m0 + warpM + m * 16 + ty;
#pragma unroll
        for (int n = 0; n < 4; n++) {
            const int col = dbase + warpN + n * 8 + tx * 2;
            if (r < cnt)
                *(float2*)&g_y[((size_t)e * NT + r) * ND + col] =
                    make_float2(acc[m][n][0], acc[m][n][1]);
            if (r + 8 < cnt)
                *(float2*)&g_y[((size_t)e * NT + r + 8) * ND + col] =
                    make_float2(acc[m][n][2], acc[m][n][3]);
        }
    }
}

// ===================== combine =====================
__global__ void combine_kernel(float* __restrict__ out) {
    int i = blockIdx.x * blockDim.x + threadIdx.x;
    int t = i >> 8;
    int d = (i & 255) * 4;
    int s1 = g_slot[2 * t], s2 = g_slot[2 * t + 1];
    float4 a = *(const float4*)&g_y[(size_t)s1 * ND + d];
    float4 b = *(const float4*)&g_y[(size_t)s2 * ND + d];
    *(float4*)&out[(size_t)t * ND + d] =
        make_float4(a.x + b.x, a.y + b.y, a.z + b.z, a.w + b.w);
}

// ===================== launch =====================
extern "C" void kernel_launch(void* const* d_in, const int* in_sizes, int n_in,
                              void* d_out, int out_size) {
    (void)in_sizes; (void)n_in; (void)out_size;
    const float* x  = (const float*)d_in[0];
    const float* gw = (const float*)d_in[1];
    const float* w1 = (const float*)d_in[2];
    const float* w2 = (const float*)d_in[3];
    const float* w3 = (const float*)d_in[4];
    float* out = (float*)d_out;

    const int SMEM1 = 2 * G1_BUFF * (int)sizeof(float);   // 73,728 B
    const int SMEM2 = 2 * G2_BUFF * (int)sizeof(float);   // 71,680 B
    cudaFuncSetAttribute(gemm1_tc, cudaFuncAttributeMaxDynamicSharedMemorySize, SMEM1);
    cudaFuncSetAttribute(gemm2_tc, cudaFuncAttributeMaxDynamicSharedMemorySize, SMEM2);

    init_kernel<<<1, 32>>>();
    router_kernel<<<NT / 8, 256>>>(x, gw);
    gemm1_tc<<<dim3(NE * 16, NH / 64), 256, SMEM1>>>(x, w1, w3);
    gemm2_tc<<<dim3(NE * 16, ND / 128), 256, SMEM2>>>(w2);
    combine_kernel<<<NT * ND / 4 / 256, 256>>>(out);
}

// round 6
// speedup vs baseline: 2.0025x; 1.2135x over previous
#include <cuda_runtime.h>
#include <cuda_bf16.h>
#include <cstdint>

#define NT 1024   // tokens
#define ND 1024   // model dim
#define NH 512    // hidden dim
#define NE 8      // experts

// ---- static scratch ----
__device__ int   g_cnt[NE];
__device__ int   g_tok[NE * NT];
__device__ float g_scl[NE * NT];
__device__ int   g_slot[2 * NT];
__device__ __nv_bfloat16 g_hh[(size_t)NE * NT * NH];  // hidden, hi part
__device__ __nv_bfloat16 g_hl[(size_t)NE * NT * NH];  // hidden, lo part
__device__ float g_y[(size_t)NE * NT * ND];           // 33.6 MB

// ===================== helpers =====================
// exact-ish 2-term bf16 split of a pair, packed as half2 (low = first element)
__device__ __forceinline__ void split2(float v0, float v1, uint32_t& hi, uint32_t& lo) {
    __nv_bfloat16 h0 = __float2bfloat16_rn(v0);
    __nv_bfloat16 h1 = __float2bfloat16_rn(v1);
    __nv_bfloat16 l0 = __float2bfloat16_rn(v0 - __bfloat162float(h0));
    __nv_bfloat16 l1 = __float2bfloat16_rn(v1 - __bfloat162float(h1));
    hi = (uint32_t)__bfloat16_as_ushort(h0) | ((uint32_t)__bfloat16_as_ushort(h1) << 16);
    lo = (uint32_t)__bfloat16_as_ushort(l0) | ((uint32_t)__bfloat16_as_ushort(l1) << 16);
}
__device__ __forceinline__ void mma_bf16(float* c, const uint32_t* a, uint32_t b0, uint32_t b1) {
    asm volatile(
        "mma.sync.aligned.m16n8k16.row.col.f32.bf16.bf16.f32 "
        "{%0,%1,%2,%3}, {%4,%5,%6,%7}, {%8,%9}, {%0,%1,%2,%3};"
        : "+f"(c[0]), "+f"(c[1]), "+f"(c[2]), "+f"(c[3])
        : "r"(a[0]), "r"(a[1]), "r"(a[2]), "r"(a[3]), "r"(b0), "r"(b1));
}

// ===================== init + router =====================
__global__ void init_kernel() {
    if (threadIdx.x < NE) g_cnt[threadIdx.x] = 0;
}

__global__ void router_kernel(const float* __restrict__ x,
                              const float* __restrict__ gw) {
    int t    = (blockIdx.x * blockDim.x + threadIdx.x) >> 5;
    int lane = threadIdx.x & 31;
    if (t >= NT) return;
    const float* xr = x + (size_t)t * ND;
    float acc[NE];
#pragma unroll
    for (int e = 0; e < NE; e++) acc[e] = 0.f;
    for (int d = lane; d < ND; d += 32) {
        float xv = xr[d];
        const float* g = gw + d * NE;
#pragma unroll
        for (int e = 0; e < NE; e++) acc[e] = fmaf(xv, g[e], acc[e]);
    }
#pragma unroll
    for (int e = 0; e < NE; e++)
#pragma unroll
        for (int o = 16; o > 0; o >>= 1)
            acc[e] += __shfl_xor_sync(0xffffffffu, acc[e], o);
    if (lane == 0) {
        float m = acc[0];
#pragma unroll
        for (int e = 1; e < NE; e++) m = fmaxf(m, acc[e]);
        float Z = 0.f, p[NE];
#pragma unroll
        for (int e = 0; e < NE; e++) { p[e] = __expf(acc[e] - m); Z += p[e]; }
        int i1 = 0;
#pragma unroll
        for (int e = 1; e < NE; e++) if (p[e] > p[i1]) i1 = e;
        int i2 = (i1 == 0) ? 1 : 0;
#pragma unroll
        for (int e = 0; e < NE; e++) if (e != i1 && p[e] > p[i2]) i2 = e;
        float invZ = 1.f / Z;
        int pos = atomicAdd(&g_cnt[i1], 1);
        g_tok[i1 * NT + pos] = t; g_scl[i1 * NT + pos] = p[i1] * invZ;
        g_slot[2 * t] = i1 * NT + pos;
        pos = atomicAdd(&g_cnt[i2], 1);
        g_tok[i2 * NT + pos] = t; g_scl[i2 * NT + pos] = p[i2] * invZ;
        g_slot[2 * t + 1] = i2 * NT + pos;
    }
}

// ===================== smem layout (uint32/half2 units) =====================
// A arrays: 64 rows x 20 half2 (16 used, XOR-swizzled low 2 bits of col).
// B arrays: [n][k] n-major, n rows x 20 half2 (16 k-pairs used).
#define ASTR 20
#define S1_AL  1280
#define S1_B1H 2560
#define S1_B1L 3840
#define S1_B3H 5120
#define S1_B3L 6400
#define S1_BUF 7680
#define S2_AL  1280
#define S2_BH  2560
#define S2_BL  5120
#define S2_BUF 7680

// ===================== gemm1: bf16x2-split MMA, fused SwiGLU =====================
// CTA: 64 tokens x 64 hidden, dual (w1,w3). 8 warps 2(M)x4(N), warp 32x16 each.
__global__ __launch_bounds__(256) void gemm1_tc(
    const float* __restrict__ x,
    const float* __restrict__ w1,
    const float* __restrict__ w3) {
    const int e   = blockIdx.x >> 4;
    const int mt  = blockIdx.x & 15;
    const int cnt = g_cnt[e];
    const int m0  = mt * 64;
    if (m0 >= cnt) return;
    const int hb = blockIdx.y * 64;

    extern __shared__ uint32_t smu[];
    const int tid = threadIdx.x, wid = tid >> 5, lane = tid & 31;
    const int ty = lane >> 2, tx = lane & 3;
    const int txs = tx ^ (ty & 3);                 // A-col swizzle (const per thread)
    const int warpM = (wid & 1) * 32, warpN = (wid >> 1) * 16;

    // A gather mapping: thread -> (row 0..63, 8-float k-segment)
    const int arow = tid >> 2;
    const int q4   = (tid & 3) * 4;                // half2 col base
    const int aq   = q4 * 2;                       // float col base
    const int asw  = arow & 3;
    const int gr   = m0 + arow;
    const bool av  = gr < cnt;
    const float scl = av ? g_scl[e * NT + gr] : 0.f;
    const float* ag = x + (size_t)(av ? g_tok[e * NT + gr] : 0) * ND + aq;

    // B mapping: half the threads do w1, half w3; thread -> (k-pair, n-lane)
    const int matid = tid >> 7;
    const int rem   = tid & 127;
    const int kp    = rem >> 3;                    // 0..15
    const int nlow  = rem & 7;
    const float* bg = (matid ? w3 : w1) + ((size_t)e * ND + 2 * kp) * NH + hb + nlow;
    const int bH = matid ? S1_B3H : S1_B1H;

    float a1[2][2][4], a3[2][2][4];
#pragma unroll
    for (int m = 0; m < 2; m++)
#pragma unroll
        for (int n = 0; n < 2; n++)
#pragma unroll
            for (int r = 0; r < 4; r++) { a1[m][n][r] = 0.f; a3[m][n][r] = 0.f; }

    // ---- fill chunk 0 ----
    {
        float4 v0 = *(const float4*)(ag);
        float4 v1 = *(const float4*)(ag + 4);
        float pa[8] = {v0.x*scl, v0.y*scl, v0.z*scl, v0.w*scl,
                       v1.x*scl, v1.y*scl, v1.z*scl, v1.w*scl};
        uint32_t hi, lo;
#pragma unroll
        for (int j = 0; j < 4; j++) {
            split2(pa[2*j], pa[2*j+1], hi, lo);
            smu[arow * ASTR + q4 + (j ^ asw)] = hi;
            smu[S1_AL + arow * ASTR + q4 + (j ^ asw)] = lo;
        }
#pragma unroll
        for (int j = 0; j < 8; j++) {
            int n = nlow + 8 * j;
            split2(bg[j * 8], bg[NH + j * 8], hi, lo);
            smu[bH + n * ASTR + kp] = hi;
            smu[bH + 1280 + n * ASTR + kp] = lo;
        }
    }
    __syncthreads();

    float pa[8], pb0[8], pb1[8];
    const int NC = ND / 32;
    for (int kt = 0; kt < NC; kt++) {
        const int b = kt & 1;
        const bool nxt = (kt + 1) < NC;
        if (nxt) {
            const float* agn = ag + (kt + 1) * 32;
            float4 v0 = *(const float4*)(agn);
            float4 v1 = *(const float4*)(agn + 4);
            pa[0]=v0.x*scl; pa[1]=v0.y*scl; pa[2]=v0.z*scl; pa[3]=v0.w*scl;
            pa[4]=v1.x*scl; pa[5]=v1.y*scl; pa[6]=v1.z*scl; pa[7]=v1.w*scl;
            const float* bgn = bg + (size_t)(kt + 1) * 32 * NH;
#pragma unroll
            for (int j = 0; j < 8; j++) { pb0[j] = bgn[j * 8]; pb1[j] = bgn[NH + j * 8]; }
        }

        const uint32_t* AH  = smu + b * S1_BUF;
        const uint32_t* AL  = AH + S1_AL;
        const uint32_t* B1H = AH + S1_B1H;
        const uint32_t* B1L = AH + S1_B1L;
        const uint32_t* B3H = AH + S1_B3H;
        const uint32_t* B3L = AH + S1_B3L;
#pragma unroll
        for (int k16 = 0; k16 < 2; k16++) {
            uint32_t ah[2][4], al[2][4];
#pragma unroll
            for (int m = 0; m < 2; m++) {
                const int off = (warpM + m * 16 + ty) * ASTR + k16 * 8 + txs;
                ah[m][0] = AH[off];       ah[m][1] = AH[off + 8 * ASTR];
                ah[m][2] = AH[off + 4];   ah[m][3] = AH[off + 8 * ASTR + 4];
                al[m][0] = AL[off];       al[m][1] = AL[off + 8 * ASTR];
                al[m][2] = AL[off + 4];   al[m][3] = AL[off + 8 * ASTR + 4];
            }
#pragma unroll
            for (int n = 0; n < 2; n++) {
                const int boff = (warpN + n * 8 + ty) * ASTR + k16 * 8 + tx;
                uint32_t bh0 = B1H[boff], bh1 = B1H[boff + 4];
                uint32_t bl0 = B1L[boff], bl1 = B1L[boff + 4];
#pragma unroll
                for (int m = 0; m < 2; m++) {
                    mma_bf16(a1[m][n], ah[m], bh0, bh1);
                    mma_bf16(a1[m][n], al[m], bh0, bh1);
                    mma_bf16(a1[m][n], ah[m], bl0, bl1);
                }
                bh0 = B3H[boff]; bh1 = B3H[boff + 4];
                bl0 = B3L[boff]; bl1 = B3L[boff + 4];
#pragma unroll
                for (int m = 0; m < 2; m++) {
                    mma_bf16(a3[m][n], ah[m], bh0, bh1);
                    mma_bf16(a3[m][n], al[m], bh0, bh1);
                    mma_bf16(a3[m][n], ah[m], bl0, bl1);
                }
            }
        }

        if (nxt) {
            uint32_t* D = smu + (b ^ 1) * S1_BUF;
            uint32_t hi, lo;
#pragma unroll
            for (int j = 0; j < 4; j++) {
                split2(pa[2*j], pa[2*j+1], hi, lo);
                D[arow * ASTR + q4 + (j ^ asw)] = hi;
                D[S1_AL + arow * ASTR + q4 + (j ^ asw)] = lo;
            }
#pragma unroll
            for (int j = 0; j < 8; j++) {
                int n = nlow + 8 * j;
                split2(pb0[j], pb1[j], hi, lo);
                D[bH + n * ASTR + kp] = hi;
                D[bH + 1280 + n * ASTR + kp] = lo;
            }
        }
        __syncthreads();
    }

    // epilogue: h = silu(a1)*a3, stored pre-split (bf16 hi/lo)
#pragma unroll
    for (int m = 0; m < 2; m++) {
        const int rr = m0 + warpM + m * 16 + ty;
#pragma unroll
        for (int n = 0; n < 2; n++) {
            const int col = hb + warpN + n * 8 + tx * 2;
            if (rr < cnt) {
                float g0 = a1[m][n][0], u0 = a3[m][n][0];
                float g1 = a1[m][n][1], u1 = a3[m][n][1];
                float s0 = (g0 / (1.f + __expf(-g0))) * u0;
                float s1 = (g1 / (1.f + __expf(-g1))) * u1;
                uint32_t hi, lo; split2(s0, s1, hi, lo);
                size_t idx = ((size_t)e * NT + rr) * NH + col;
                *(uint32_t*)&g_hh[idx] = hi;
                *(uint32_t*)&g_hl[idx] = lo;
            }
            if (rr + 8 < cnt) {
                float g0 = a1[m][n][2], u0 = a3[m][n][2];
                float g1 = a1[m][n][3], u1 = a3[m][n][3];
                float s0 = (g0 / (1.f + __expf(-g0))) * u0;
                float s1 = (g1 / (1.f + __expf(-g1))) * u1;
                uint32_t hi, lo; split2(s0, s1, hi, lo);
                size_t idx = ((size_t)e * NT + rr + 8) * NH + col;
                *(uint32_t*)&g_hh[idx] = hi;
                *(uint32_t*)&g_hl[idx] = lo;
            }
        }
    }
}

// ===================== gemm2: y = h @ w2 (bf16x2-split) =====================
// CTA: 64 x 128. 8 warps 2x4; warp 32x32.
__global__ __launch_bounds__(256) void gemm2_tc(const float* __restrict__ w2) {
    const int e   = blockIdx.x >> 4;
    const int mt  = blockIdx.x & 15;
    const int cnt = g_cnt[e];
    const int m0  = mt * 64;
    if (m0 >= cnt) return;
    const int dbase = blockIdx.y * 128;

    extern __shared__ uint32_t smu[];
    const int tid = threadIdx.x, wid = tid >> 5, lane = tid & 31;
    const int ty = lane >> 2, tx = lane & 3;
    const int txs = tx ^ (ty & 3);
    const int warpM = (wid & 1) * 32, warpN = (wid >> 1) * 32;

    // A copy mapping (pre-split bf16 in g_hh/g_hl, expert-local contiguous rows)
    const int arow = tid >> 2;
    const int q4   = (tid & 3) * 4;
    const int aq   = q4 * 2;
    const int asw  = arow & 3;
    const __nv_bfloat16* ahh = g_hh + ((size_t)e * NT + m0 + arow) * NH + aq;
    const __nv_bfloat16* ahl = g_hl + ((size_t)e * NT + m0 + arow) * NH + aq;

    // B mapping: thread -> (k-pair 0..15, n-lane 0..15)
    const int kp   = tid >> 4;
    const int nlow = tid & 15;
    const float* bg = w2 + ((size_t)e * NH + 2 * kp) * ND + dbase + nlow;

    float acc[2][4][4];
#pragma unroll
    for (int m = 0; m < 2; m++)
#pragma unroll
        for (int n = 0; n < 4; n++)
#pragma unroll
            for (int r = 0; r < 4; r++) acc[m][n][r] = 0.f;

    // ---- fill chunk 0 ----
    {
        uint4 vh = *(const uint4*)(ahh);
        uint4 vl = *(const uint4*)(ahl);
        smu[arow * ASTR + q4 + (0 ^ asw)] = vh.x;
        smu[arow * ASTR + q4 + (1 ^ asw)] = vh.y;
        smu[arow * ASTR + q4 + (2 ^ asw)] = vh.z;
        smu[arow * ASTR + q4 + (3 ^ asw)] = vh.w;
        smu[S2_AL + arow * ASTR + q4 + (0 ^ asw)] = vl.x;
        smu[S2_AL + arow * ASTR + q4 + (1 ^ asw)] = vl.y;
        smu[S2_AL + arow * ASTR + q4 + (2 ^ asw)] = vl.z;
        smu[S2_AL + arow * ASTR + q4 + (3 ^ asw)] = vl.w;
        uint32_t hi, lo;
#pragma unroll
        for (int j = 0; j < 8; j++) {
            int n = nlow + 16 * j;
            split2(bg[n - nlow + nlow], bg[ND + n - nlow + nlow], hi, lo);  // rows 2kp, 2kp+1
            // (simplify: addresses below)
            split2(bg[16 * j], bg[ND + 16 * j], hi, lo);
            smu[S2_BH + n * ASTR + kp] = hi;
            smu[S2_BL + n * ASTR + kp] = lo;
        }
    }
    __syncthreads();

    uint4 pah, pal; float pb0[8], pb1[8];
    const int NC = NH / 32;
    for (int kt = 0; kt < NC; kt++) {
        const int b = kt & 1;
        const bool nxt = (kt + 1) < NC;
        if (nxt) {
            pah = *(const uint4*)(ahh + (kt + 1) * 32);
            pal = *(const uint4*)(ahl + (kt + 1) * 32);
            const float* bgn = bg + (size_t)(kt + 1) * 32 * ND;
#pragma unroll
            for (int j = 0; j < 8; j++) { pb0[j] = bgn[16 * j]; pb1[j] = bgn[ND + 16 * j]; }
        }

        const uint32_t* AH = smu + b * S2_BUF;
        const uint32_t* AL = AH + S2_AL;
        const uint32_t* BH = AH + S2_BH;
        const uint32_t* BL = AH + S2_BL;
#pragma unroll
        for (int k16 = 0; k16 < 2; k16++) {
            uint32_t ah[2][4], al[2][4];
#pragma unroll
            for (int m = 0; m < 2; m++) {
                const int off = (warpM + m * 16 + ty) * ASTR + k16 * 8 + txs;
                ah[m][0] = AH[off];       ah[m][1] = AH[off + 8 * ASTR];
                ah[m][2] = AH[off + 4];   ah[m][3] = AH[off + 8 * ASTR + 4];
                al[m][0] = AL[off];       al[m][1] = AL[off + 8 * ASTR];
                al[m][2] = AL[off + 4];   al[m][3] = AL[off + 8 * ASTR + 4];
            }
#pragma unroll
            for (int n = 0; n < 4; n++) {
                const int boff = (warpN + n * 8 + ty) * ASTR + k16 * 8 + tx;
                uint32_t bh0 = BH[boff], bh1 = BH[boff + 4];
                uint32_t bl0 = BL[boff], bl1 = BL[boff + 4];
#pragma unroll
                for (int m = 0; m < 2; m++) {
                    mma_bf16(acc[m][n], ah[m], bh0, bh1);
                    mma_bf16(acc[m][n], al[m], bh0, bh1);
                    mma_bf16(acc[m][n], ah[m], bl0, bl1);
                }
            }
        }

        if (nxt) {
            uint32_t* D = smu + (b ^ 1) * S2_BUF;
            D[arow * ASTR + q4 + (0 ^ asw)] = pah.x;
            D[arow * ASTR + q4 + (1 ^ asw)] = pah.y;
            D[arow * ASTR + q4 + (2 ^ asw)] = pah.z;
            D[arow * ASTR + q4 + (3 ^ asw)] = pah.w;
            D[S2_AL + arow * ASTR + q4 + (0 ^ asw)] = pal.x;
            D[S2_AL + arow * ASTR + q4 + (1 ^ asw)] = pal.y;
            D[S2_AL + arow * ASTR + q4 + (2 ^ asw)] = pal.z;
            D[S2_AL + arow * ASTR + q4 + (3 ^ asw)] = pal.w;
            uint32_t hi, lo;
#pragma unroll
            for (int j = 0; j < 8; j++) {
                int n = nlow + 16 * j;
                split2(pb0[j], pb1[j], hi, lo);
                D[S2_BH + n * ASTR + kp] = hi;
                D[S2_BL + n * ASTR + kp] = lo;
            }
        }
        __syncthreads();
    }

    // epilogue: f32 y rows, combined later
#pragma unroll
    for (int m = 0; m < 2; m++) {
        const int rr = m0 + warpM + m * 16 + ty;
#pragma unroll
        for (int n = 0; n < 4; n++) {
            const int col = dbase + warpN + n * 8 + tx * 2;
            if (rr < cnt)
                *(float2*)&g_y[((size_t)e * NT + rr) * ND + col] =
                    make_float2(acc[m][n][0], acc[m][n][1]);
            if (rr + 8 < cnt)
                *(float2*)&g_y[((size_t)e * NT + rr + 8) * ND + col] =
                    make_float2(acc[m][n][2], acc[m][n][3]);
        }
    }
}

// ===================== combine =====================
__global__ void combine_kernel(float* __restrict__ out) {
    int i = blockIdx.x * blockDim.x + threadIdx.x;
    int t = i >> 8;
    int d = (i & 255) * 4;
    int s1 = g_slot[2 * t], s2 = g_slot[2 * t + 1];
    float4 a = *(const float4*)&g_y[(size_t)s1 * ND + d];
    float4 b = *(const float4*)&g_y[(size_t)s2 * ND + d];
    *(float4*)&out[(size_t)t * ND + d] =
        make_float4(a.x + b.x, a.y + b.y, a.z + b.z, a.w + b.w);
}

// ===================== launch =====================
extern "C" void kernel_launch(void* const* d_in, const int* in_sizes, int n_in,
                              void* d_out, int out_size) {
    (void)in_sizes; (void)n_in; (void)out_size;
    const float* x  = (const float*)d_in[0];
    const float* gw = (const float*)d_in[1];
    const float* w1 = (const float*)d_in[2];
    const float* w2 = (const float*)d_in[3];
    const float* w3 = (const float*)d_in[4];
    float* out = (float*)d_out;

    const int SMEM1 = 2 * S1_BUF * 4;   // 61440 B
    const int SMEM2 = 2 * S2_BUF * 4;   // 61440 B
    cudaFuncSetAttribute(gemm1_tc, cudaFuncAttributeMaxDynamicSharedMemorySize, SMEM1);
    cudaFuncSetAttribute(gemm2_tc, cudaFuncAttributeMaxDynamicSharedMemorySize, SMEM2);

    init_kernel<<<1, 32>>>();
    router_kernel<<<NT / 8, 256>>>(x, gw);
    gemm1_tc<<<dim3(NE * 16, NH / 64), 256, SMEM1>>>(x, w1, w3);
    gemm2_tc<<<dim3(NE * 16, ND / 128), 256, SMEM2>>>(w2);
    combine_kernel<<<NT * ND / 4 / 256, 256>>>(out);
}

// round 7
// speedup vs baseline: 2.2014x; 1.0993x over previous
#include <cuda_runtime.h>
#include <cuda_bf16.h>
#include <cstdint>

#define NT 1024   // tokens
#define ND 1024   // model dim
#define NH 512    // hidden dim
#define NE 8      // experts

// ---- static scratch ----
__device__ int   g_cnt[NE];
__device__ int   g_tok[NE * NT];
__device__ float g_scl[NE * NT];
__device__ __nv_bfloat16 g_hh[(size_t)NE * NT * NH];  // hidden, hi part
__device__ __nv_bfloat16 g_hl[(size_t)NE * NT * NH];  // hidden, lo part

// ===================== helpers =====================
__device__ __forceinline__ void split2(float v0, float v1, uint32_t& hi, uint32_t& lo) {
    __nv_bfloat16 h0 = __float2bfloat16_rn(v0);
    __nv_bfloat16 h1 = __float2bfloat16_rn(v1);
    __nv_bfloat16 l0 = __float2bfloat16_rn(v0 - __bfloat162float(h0));
    __nv_bfloat16 l1 = __float2bfloat16_rn(v1 - __bfloat162float(h1));
    hi = (uint32_t)__bfloat16_as_ushort(h0) | ((uint32_t)__bfloat16_as_ushort(h1) << 16);
    lo = (uint32_t)__bfloat16_as_ushort(l0) | ((uint32_t)__bfloat16_as_ushort(l1) << 16);
}
__device__ __forceinline__ void mma_bf16(float* c, const uint32_t* a, uint32_t b0, uint32_t b1) {
    asm volatile(
        "mma.sync.aligned.m16n8k16.row.col.f32.bf16.bf16.f32 "
        "{%0,%1,%2,%3}, {%4,%5,%6,%7}, {%8,%9}, {%0,%1,%2,%3};"
        : "+f"(c[0]), "+f"(c[1]), "+f"(c[2]), "+f"(c[3])
        : "r"(a[0]), "r"(a[1]), "r"(a[2]), "r"(a[3]), "r"(b0), "r"(b1));
}
__device__ __forceinline__ void ldm_x4(uint32_t* r, uint32_t addr) {
    asm volatile("ldmatrix.sync.aligned.m8n8.x4.shared.b16 {%0,%1,%2,%3}, [%4];"
        : "=r"(r[0]), "=r"(r[1]), "=r"(r[2]), "=r"(r[3]) : "r"(addr));
}

// ===================== init + router =====================
__global__ void init_kernel(float* __restrict__ out) {
    int tid = blockIdx.x * blockDim.x + threadIdx.x;
    if (tid < NE) g_cnt[tid] = 0;
    int stride = gridDim.x * blockDim.x;
    for (int i = tid; i < NT * ND / 4; i += stride)
        *(float4*)&out[i * 4] = make_float4(0.f, 0.f, 0.f, 0.f);
}

__global__ void router_kernel(const float* __restrict__ x,
                              const float* __restrict__ gw) {
    int t    = (blockIdx.x * blockDim.x + threadIdx.x) >> 5;
    int lane = threadIdx.x & 31;
    if (t >= NT) return;
    const float* xr = x + (size_t)t * ND;
    float acc[NE];
#pragma unroll
    for (int e = 0; e < NE; e++) acc[e] = 0.f;
    for (int d = lane; d < ND; d += 32) {
        float xv = xr[d];
        const float* g = gw + d * NE;
#pragma unroll
        for (int e = 0; e < NE; e++) acc[e] = fmaf(xv, g[e], acc[e]);
    }
#pragma unroll
    for (int e = 0; e < NE; e++)
#pragma unroll
        for (int o = 16; o > 0; o >>= 1)
            acc[e] += __shfl_xor_sync(0xffffffffu, acc[e], o);
    if (lane == 0) {
        float m = acc[0];
#pragma unroll
        for (int e = 1; e < NE; e++) m = fmaxf(m, acc[e]);
        float Z = 0.f, p[NE];
#pragma unroll
        for (int e = 0; e < NE; e++) { p[e] = __expf(acc[e] - m); Z += p[e]; }
        int i1 = 0;
#pragma unroll
        for (int e = 1; e < NE; e++) if (p[e] > p[i1]) i1 = e;
        int i2 = (i1 == 0) ? 1 : 0;
#pragma unroll
        for (int e = 0; e < NE; e++) if (e != i1 && p[e] > p[i2]) i2 = e;
        float invZ = 1.f / Z;
        int pos = atomicAdd(&g_cnt[i1], 1);
        g_tok[i1 * NT + pos] = t; g_scl[i1 * NT + pos] = p[i1] * invZ;
        pos = atomicAdd(&g_cnt[i2], 1);
        g_tok[i2 * NT + pos] = t; g_scl[i2 * NT + pos] = p[i2] * invZ;
    }
}

// ===================== smem layout (uint32/half2 units, stride 20) =====================
#define ASTR 20
#define S1_AL  1280
#define S1_B1H 2560
#define S1_B1L 3840
#define S1_B3H 5120
#define S1_B3L 6400
#define S1_BUF 7680
#define S2_AL  1280
#define S2_BH  2560
#define S2_BL  5120
#define S2_BUF 7680

// ===================== gemm1: bf16-split + ldmatrix, fused SwiGLU =====================
// CTA: 64 tokens x 64 hidden, dual (w1,w3). 8 warps 2(M)x4(N), warp 32x16 each.
__global__ __launch_bounds__(256) void gemm1_tc(
    const float* __restrict__ x,
    const float* __restrict__ w1,
    const float* __restrict__ w3) {
    const int e   = blockIdx.x >> 4;
    const int mt  = blockIdx.x & 15;
    const int cnt = g_cnt[e];
    const int m0  = mt * 64;
    if (m0 >= cnt) return;
    const int hb = blockIdx.y * 64;

    extern __shared__ uint32_t smu[];
    const uint32_t sb = (uint32_t)__cvta_generic_to_shared(smu);
    const int tid = threadIdx.x, wid = tid >> 5, lane = tid & 31;
    const int ty = lane >> 2, tx = lane & 3;
    const int warpM = (wid & 1) * 32, warpN = (wid >> 1) * 16;

    // ldmatrix per-lane base addresses
    const int a_r = (lane & 7) + ((lane >> 3) & 1) * 8;
    const int a_c = ((lane >> 4) & 1) * 4;
    const uint32_t aAddr = sb + (uint32_t)(((warpM + a_r) * ASTR + a_c) * 4);
    const int b_r = (lane & 7) + ((lane >> 4) & 1) * 8;
    const int b_c = ((lane >> 3) & 1) * 4;
    const uint32_t bAddr = sb + (uint32_t)(((warpN + b_r) * ASTR + b_c) * 4);

    // A gather: thread -> (row 0..63, 8-float k-segment)
    const int arow = tid >> 2;
    const int q4   = (tid & 3) * 4;
    const int aq   = q4 * 2;
    const int gr   = m0 + arow;
    const bool av  = gr < cnt;
    const float scl = av ? g_scl[e * NT + gr] : 0.f;
    const float* ag = x + (size_t)(av ? g_tok[e * NT + gr] : 0) * ND + aq;

    // B producer: half threads w1, half w3; thread -> (k-pair, n-lane)
    const int matid = tid >> 7;
    const int rem   = tid & 127;
    const int kp    = rem >> 3;                    // 0..15
    const int nlow  = rem & 7;
    const float* bg = (matid ? w3 : w1) + ((size_t)e * ND + 2 * kp) * NH + hb + nlow;
    const int bH = matid ? S1_B3H : S1_B1H;

    float a1[2][2][4], a3[2][2][4];
#pragma unroll
    for (int m = 0; m < 2; m++)
#pragma unroll
        for (int n = 0; n < 2; n++)
#pragma unroll
            for (int r = 0; r < 4; r++) { a1[m][n][r] = 0.f; a3[m][n][r] = 0.f; }

    // ---- fill chunk 0 ----
    {
        float4 v0 = *(const float4*)(ag);
        float4 v1 = *(const float4*)(ag + 4);
        float pa[8] = {v0.x*scl, v0.y*scl, v0.z*scl, v0.w*scl,
                       v1.x*scl, v1.y*scl, v1.z*scl, v1.w*scl};
        uint32_t hi, lo;
#pragma unroll
        for (int j = 0; j < 4; j++) {
            split2(pa[2*j], pa[2*j+1], hi, lo);
            smu[arow * ASTR + q4 + j] = hi;
            smu[S1_AL + arow * ASTR + q4 + j] = lo;
        }
#pragma unroll
        for (int j = 0; j < 8; j++) {
            int n = nlow + 8 * j;
            split2(bg[j * 8], bg[NH + j * 8], hi, lo);
            smu[bH + n * ASTR + kp] = hi;
            smu[bH + 1280 + n * ASTR + kp] = lo;
        }
    }
    __syncthreads();

    float pa[8], pb0[8], pb1[8];
    const int NC = ND / 32;
    for (int kt = 0; kt < NC; kt++) {
        const int b = kt & 1;
        const bool nxt = (kt + 1) < NC;
        if (nxt) {
            const float* agn = ag + (kt + 1) * 32;
            float4 v0 = *(const float4*)(agn);
            float4 v1 = *(const float4*)(agn + 4);
            pa[0]=v0.x*scl; pa[1]=v0.y*scl; pa[2]=v0.z*scl; pa[3]=v0.w*scl;
            pa[4]=v1.x*scl; pa[5]=v1.y*scl; pa[6]=v1.z*scl; pa[7]=v1.w*scl;
            const float* bgn = bg + (size_t)(kt + 1) * 32 * NH;
#pragma unroll
            for (int j = 0; j < 8; j++) { pb0[j] = bgn[j * 8]; pb1[j] = bgn[NH + j * 8]; }
        }

        const uint32_t bufB = (uint32_t)(b * S1_BUF * 4);
#pragma unroll
        for (int k16 = 0; k16 < 2; k16++) {
            const uint32_t kOff = bufB + (uint32_t)(k16 * 8 * 4);
            uint32_t ah[2][4], al[2][4];
#pragma unroll
            for (int m = 0; m < 2; m++) {
                ldm_x4(ah[m], aAddr + kOff + (uint32_t)(m * 16 * ASTR * 4));
                ldm_x4(al[m], aAddr + kOff + (uint32_t)((S1_AL + m * 16 * ASTR) * 4));
            }
            uint32_t b1h[4], b1l[4], b3h[4], b3l[4];
            ldm_x4(b1h, bAddr + kOff + (uint32_t)(S1_B1H * 4));
            ldm_x4(b1l, bAddr + kOff + (uint32_t)(S1_B1L * 4));
            ldm_x4(b3h, bAddr + kOff + (uint32_t)(S1_B3H * 4));
            ldm_x4(b3l, bAddr + kOff + (uint32_t)(S1_B3L * 4));
#pragma unroll
            for (int n = 0; n < 2; n++) {
#pragma unroll
                for (int m = 0; m < 2; m++) {
                    mma_bf16(a1[m][n], ah[m], b1h[2*n], b1h[2*n+1]);
                    mma_bf16(a1[m][n], al[m], b1h[2*n], b1h[2*n+1]);
                    mma_bf16(a1[m][n], ah[m], b1l[2*n], b1l[2*n+1]);
                    mma_bf16(a3[m][n], ah[m], b3h[2*n], b3h[2*n+1]);
                    mma_bf16(a3[m][n], al[m], b3h[2*n], b3h[2*n+1]);
                    mma_bf16(a3[m][n], ah[m], b3l[2*n], b3l[2*n+1]);
                }
            }
        }

        if (nxt) {
            uint32_t* D = smu + (b ^ 1) * S1_BUF;
            uint32_t hi, lo;
#pragma unroll
            for (int j = 0; j < 4; j++) {
                split2(pa[2*j], pa[2*j+1], hi, lo);
                D[arow * ASTR + q4 + j] = hi;
                D[S1_AL + arow * ASTR + q4 + j] = lo;
            }
#pragma unroll
            for (int j = 0; j < 8; j++) {
                int n = nlow + 8 * j;
                split2(pb0[j], pb1[j], hi, lo);
                D[bH + n * ASTR + kp] = hi;
                D[bH + 1280 + n * ASTR + kp] = lo;
            }
        }
        __syncthreads();
    }

    // epilogue: h = silu(a1)*a3, stored pre-split (bf16 hi/lo)
#pragma unroll
    for (int m = 0; m < 2; m++) {
        const int rr = m0 + warpM + m * 16 + ty;
#pragma unroll
        for (int n = 0; n < 2; n++) {
            const int col = hb + warpN + n * 8 + tx * 2;
            if (rr < cnt) {
                float g0 = a1[m][n][0], u0 = a3[m][n][0];
                float g1 = a1[m][n][1], u1 = a3[m][n][1];
                float s0 = (g0 / (1.f + __expf(-g0))) * u0;
                float s1 = (g1 / (1.f + __expf(-g1))) * u1;
                uint32_t hi, lo; split2(s0, s1, hi, lo);
                size_t idx = ((size_t)e * NT + rr) * NH + col;
                *(uint32_t*)&g_hh[idx] = hi;
                *(uint32_t*)&g_hl[idx] = lo;
            }
            if (rr + 8 < cnt) {
                float g0 = a1[m][n][2], u0 = a3[m][n][2];
                float g1 = a1[m][n][3], u1 = a3[m][n][3];
                float s0 = (g0 / (1.f + __expf(-g0))) * u0;
                float s1 = (g1 / (1.f + __expf(-g1))) * u1;
                uint32_t hi, lo; split2(s0, s1, hi, lo);
                size_t idx = ((size_t)e * NT + rr + 8) * NH + col;
                *(uint32_t*)&g_hh[idx] = hi;
                *(uint32_t*)&g_hl[idx] = lo;
            }
        }
    }
}

// ===================== gemm2: y = h @ w2, atomic scatter-combine =====================
// CTA: 64 x 128. 8 warps 2x4; warp 32x32.
__global__ __launch_bounds__(256) void gemm2_tc(const float* __restrict__ w2,
                                                float* __restrict__ out) {
    const int e   = blockIdx.x >> 4;
    const int mt  = blockIdx.x & 15;
    const int cnt = g_cnt[e];
    const int m0  = mt * 64;
    if (m0 >= cnt) return;
    const int dbase = blockIdx.y * 128;

    extern __shared__ uint32_t smu[];
    const uint32_t sb = (uint32_t)__cvta_generic_to_shared(smu);
    const int tid = threadIdx.x, wid = tid >> 5, lane = tid & 31;
    const int ty = lane >> 2, tx = lane & 3;
    const int warpM = (wid & 1) * 32, warpN = (wid >> 1) * 32;

    const int a_r = (lane & 7) + ((lane >> 3) & 1) * 8;
    const int a_c = ((lane >> 4) & 1) * 4;
    const uint32_t aAddr = sb + (uint32_t)(((warpM + a_r) * ASTR + a_c) * 4);
    const int b_r = (lane & 7) + ((lane >> 4) & 1) * 8;
    const int b_c = ((lane >> 3) & 1) * 4;
    const uint32_t bAddr = sb + (uint32_t)(((warpN + b_r) * ASTR + b_c) * 4);

    // A copy (pre-split bf16, expert-local contiguous rows)
    const int arow = tid >> 2;
    const int q4   = (tid & 3) * 4;
    const int aq   = q4 * 2;
    const __nv_bfloat16* ahh = g_hh + ((size_t)e * NT + m0 + arow) * NH + aq;
    const __nv_bfloat16* ahl = g_hl + ((size_t)e * NT + m0 + arow) * NH + aq;

    // B producer: thread -> (k-pair 0..15, n-lane 0..15)
    const int kp   = tid >> 4;
    const int nlow = tid & 15;
    const float* bg = w2 + ((size_t)e * NH + 2 * kp) * ND + dbase + nlow;

    float acc[2][4][4];
#pragma unroll
    for (int m = 0; m < 2; m++)
#pragma unroll
        for (int n = 0; n < 4; n++)
#pragma unroll
            for (int r = 0; r < 4; r++) acc[m][n][r] = 0.f;

    // ---- fill chunk 0 ----
    {
        uint4 vh = *(const uint4*)(ahh);
        uint4 vl = *(const uint4*)(ahl);
        *(uint4*)&smu[arow * ASTR + q4] = vh;
        *(uint4*)&smu[S2_AL + arow * ASTR + q4] = vl;
        uint32_t hi, lo;
#pragma unroll
        for (int j = 0; j < 8; j++) {
            int n = nlow + 16 * j;
            split2(bg[16 * j], bg[ND + 16 * j], hi, lo);
            smu[S2_BH + n * ASTR + kp] = hi;
            smu[S2_BL + n * ASTR + kp] = lo;
        }
    }
    __syncthreads();

    uint4 pah, pal; float pb0[8], pb1[8];
    const int NC = NH / 32;
    for (int kt = 0; kt < NC; kt++) {
        const int b = kt & 1;
        const bool nxt = (kt + 1) < NC;
        if (nxt) {
            pah = *(const uint4*)(ahh + (kt + 1) * 32);
            pal = *(const uint4*)(ahl + (kt + 1) * 32);
            const float* bgn = bg + (size_t)(kt + 1) * 32 * ND;
#pragma unroll
            for (int j = 0; j < 8; j++) { pb0[j] = bgn[16 * j]; pb1[j] = bgn[ND + 16 * j]; }
        }

        const uint32_t bufB = (uint32_t)(b * S2_BUF * 4);
#pragma unroll
        for (int k16 = 0; k16 < 2; k16++) {
            const uint32_t kOff = bufB + (uint32_t)(k16 * 8 * 4);
            uint32_t ah[2][4], al[2][4];
#pragma unroll
            for (int m = 0; m < 2; m++) {
                ldm_x4(ah[m], aAddr + kOff + (uint32_t)(m * 16 * ASTR * 4));
                ldm_x4(al[m], aAddr + kOff + (uint32_t)((S2_AL + m * 16 * ASTR) * 4));
            }
            uint32_t bh[2][4], bl[2][4];
#pragma unroll
            for (int g = 0; g < 2; g++) {
                ldm_x4(bh[g], bAddr + kOff + (uint32_t)((S2_BH + g * 16 * ASTR) * 4));
                ldm_x4(bl[g], bAddr + kOff + (uint32_t)((S2_BL + g * 16 * ASTR) * 4));
            }
#pragma unroll
            for (int n = 0; n < 4; n++) {
                uint32_t h0 = bh[n >> 1][(n & 1) * 2], h1 = bh[n >> 1][(n & 1) * 2 + 1];
                uint32_t l0 = bl[n >> 1][(n & 1) * 2], l1 = bl[n >> 1][(n & 1) * 2 + 1];
#pragma unroll
                for (int m = 0; m < 2; m++) {
                    mma_bf16(acc[m][n], ah[m], h0, h1);
                    mma_bf16(acc[m][n], al[m], h0, h1);
                    mma_bf16(acc[m][n], ah[m], l0, l1);
                }
            }
        }

        if (nxt) {
            uint32_t* D = smu + (b ^ 1) * S2_BUF;
            *(uint4*)&D[arow * ASTR + q4] = pah;
            *(uint4*)&D[S2_AL + arow * ASTR + q4] = pal;
            uint32_t hi, lo;
#pragma unroll
            for (int j = 0; j < 8; j++) {
                int n = nlow + 16 * j;
                split2(pb0[j], pb1[j], hi, lo);
                D[S2_BH + n * ASTR + kp] = hi;
                D[S2_BL + n * ASTR + kp] = lo;
            }
        }
        __syncthreads();
    }

    // epilogue: atomic scatter-add into out (exactly 2 contributions/element)
#pragma unroll
    for (int m = 0; m < 2; m++) {
        const int r0 = m0 + warpM + m * 16 + ty;
        const int r1 = r0 + 8;
        const int tok0 = (r0 < cnt) ? g_tok[e * NT + r0] : -1;
        const int tok1 = (r1 < cnt) ? g_tok[e * NT + r1] : -1;
#pragma unroll
        for (int n = 0; n < 4; n++) {
            const int col = dbase + warpN + n * 8 + tx * 2;
            if (tok0 >= 0) {
                float* op = out + (size_t)tok0 * ND + col;
                atomicAdd(op,     acc[m][n][0]);
                atomicAdd(op + 1, acc[m][n][1]);
            }
            if (tok1 >= 0) {
                float* op = out + (size_t)tok1 * ND + col;
                atomicAdd(op,     acc[m][n][2]);
                atomicAdd(op + 1, acc[m][n][3]);
            }
        }
    }
}

// ===================== launch =====================
extern "C" void kernel_launch(void* const* d_in, const int* in_sizes, int n_in,
                              void* d_out, int out_size) {
    (void)in_sizes; (void)n_in; (void)out_size;
    const float* x  = (const float*)d_in[0];
    const float* gw = (const float*)d_in[1];
    const float* w1 = (const float*)d_in[2];
    const float* w2 = (const float*)d_in[3];
    const float* w3 = (const float*)d_in[4];
    float* out = (float*)d_out;

    const int SMEM1 = 2 * S1_BUF * 4;   // 61440 B
    const int SMEM2 = 2 * S2_BUF * 4;   // 61440 B
    cudaFuncSetAttribute(gemm1_tc, cudaFuncAttributeMaxDynamicSharedMemorySize, SMEM1);
    cudaFuncSetAttribute(gemm2_tc, cudaFuncAttributeMaxDynamicSharedMemorySize, SMEM2);

    init_kernel<<<256, 256>>>(out);
    router_kernel<<<NT / 8, 256>>>(x, gw);
    gemm1_tc<<<dim3(NE * 16, NH / 64), 256, SMEM1>>>(x, w1, w3);
    gemm2_tc<<<dim3(NE * 16, ND / 128), 256, SMEM2>>>(w2, out);
}